// round 1
// baseline (speedup 1.0000x reference)
#include <cuda_runtime.h>
#include <math.h>

#define NN 100000
#define NE 3200000
#define NC 16

// Scratch (device globals — no allocation allowed in kernel_launch)
__device__ float  g_deg[NN];
__device__ float  g_dinv[NN];
__device__ double g_sum;
__device__ int    g_is64;

// ---------------------------------------------------------------------------
// Kernel 1: zero degree + sum, and detect edge_index dtype.
// int64 little-endian positive values < 100000 => every odd 32-bit word is 0.
// Probability that 32 random int32 node indices are all zero: ~(1e-5)^32 = 0.
// ---------------------------------------------------------------------------
__global__ void init_kernel(const unsigned int* __restrict__ ei_words) {
    int i = blockIdx.x * blockDim.x + threadIdx.x;
    if (i < NN) g_deg[i] = 0.0f;
    if (i == 0) {
        g_sum = 0.0;
        int is64 = 1;
        #pragma unroll
        for (int k = 1; k < 64; k += 2)
            if (ei_words[k] != 0u) is64 = 0;
        g_is64 = is64;
    }
}

// ---------------------------------------------------------------------------
// Kernel 2: degree = segment_sum(edge_weights, row). 4 edges/thread,
// vectorized loads, spread global atomics (REDG fast path).
// ---------------------------------------------------------------------------
__global__ void degree_kernel(const void* __restrict__ ei,
                              const float4* __restrict__ w4) {
    int t = blockIdx.x * blockDim.x + threadIdx.x;
    if (t >= NE / 4) return;
    float4 w = w4[t];
    int r0, r1, r2, r3;
    if (g_is64) {
        const longlong2* p = (const longlong2*)ei;
        longlong2 a = p[2 * t], b = p[2 * t + 1];
        r0 = (int)a.x; r1 = (int)a.y; r2 = (int)b.x; r3 = (int)b.y;
    } else {
        int4 a = ((const int4*)ei)[t];
        r0 = a.x; r1 = a.y; r2 = a.z; r3 = a.w;
    }
    atomicAdd(&g_deg[r0], w.x);
    atomicAdd(&g_deg[r1], w.y);
    atomicAdd(&g_deg[r2], w.z);
    atomicAdd(&g_deg[r3], w.w);
}

// ---------------------------------------------------------------------------
// Kernel 3: dinv = 1/sqrt(degree)
// ---------------------------------------------------------------------------
__global__ void rsqrt_kernel() {
    int i = blockIdx.x * blockDim.x + threadIdx.x;
    if (i < NN) g_dinv[i] = rsqrtf(g_deg[i]);
}

// ---------------------------------------------------------------------------
// Kernel 4: per-edge p-norm (P=2), weighted, reduced to a scalar.
// 4 edges/thread; y rows gathered as 4x float4 (64B each, L2-resident).
// ---------------------------------------------------------------------------
__global__ void __launch_bounds__(256)
edge_kernel(const void* __restrict__ ei,
            const float4* __restrict__ w4,
            const float4* __restrict__ y) {
    int t = blockIdx.x * blockDim.x + threadIdx.x;
    float acc = 0.0f;
    if (t < NE / 4) {
        int r[4], c[4];
        if (g_is64) {
            const longlong2* p = (const longlong2*)ei;       // rows
            const longlong2* q = p + (NE / 2);               // cols (offset NE int64)
            longlong2 a = p[2 * t], b = p[2 * t + 1];
            longlong2 e = q[2 * t], f = q[2 * t + 1];
            r[0] = (int)a.x; r[1] = (int)a.y; r[2] = (int)b.x; r[3] = (int)b.y;
            c[0] = (int)e.x; c[1] = (int)e.y; c[2] = (int)f.x; c[3] = (int)f.y;
        } else {
            const int4* p = (const int4*)ei;
            int4 a = p[t];
            int4 b = p[NE / 4 + t];
            r[0] = a.x; r[1] = a.y; r[2] = a.z; r[3] = a.w;
            c[0] = b.x; c[1] = b.y; c[2] = b.z; c[3] = b.w;
        }
        float4 wv4 = w4[t];
        float wv[4] = {wv4.x, wv4.y, wv4.z, wv4.w};
        #pragma unroll
        for (int e = 0; e < 4; e++) {
            float dr = g_dinv[r[e]];
            float dc = g_dinv[c[e]];
            const float4* yr = y + (size_t)r[e] * 4;
            const float4* yc = y + (size_t)c[e] * 4;
            float s = 0.0f;
            #pragma unroll
            for (int k = 0; k < 4; k++) {
                float4 a4 = yr[k];
                float4 b4 = yc[k];
                float d0 = a4.x * dr - b4.x * dc;
                float d1 = a4.y * dr - b4.y * dc;
                float d2 = a4.z * dr - b4.z * dc;
                float d3 = a4.w * dr - b4.w * dc;
                s += d0 * d0 + d1 * d1 + d2 * d2 + d3 * d3;
            }
            acc += sqrtf(s) * wv[e];
        }
    }
    // warp reduce
    #pragma unroll
    for (int off = 16; off; off >>= 1)
        acc += __shfl_down_sync(0xffffffffu, acc, off);
    __shared__ float warp_sums[8];
    int lane = threadIdx.x & 31;
    int wid  = threadIdx.x >> 5;
    if (lane == 0) warp_sums[wid] = acc;
    __syncthreads();
    if (wid == 0) {
        float v = (lane < 8) ? warp_sums[lane] : 0.0f;
        #pragma unroll
        for (int off = 4; off; off >>= 1)
            v += __shfl_down_sync(0xffffffffu, v, off);
        if (lane == 0) atomicAdd(&g_sum, (double)v);
    }
}

// ---------------------------------------------------------------------------
// Kernel 5: mean
// ---------------------------------------------------------------------------
__global__ void finalize_kernel(float* __restrict__ out) {
    out[0] = (float)(g_sum / (double)NE);
}

extern "C" void kernel_launch(void* const* d_in, const int* in_sizes, int n_in,
                              void* d_out, int out_size) {
    const void*  ei = d_in[0];                  // edge_index (2, NE) int64 or int32
    const float* w  = (const float*)d_in[1];    // edge_weights (NE,)
    const float* y  = (const float*)d_in[2];    // y (NN, 16)

    init_kernel<<<(NN + 255) / 256, 256>>>((const unsigned int*)ei);
    degree_kernel<<<NE / 4 / 256, 256>>>(ei, (const float4*)w);
    rsqrt_kernel<<<(NN + 255) / 256, 256>>>();
    edge_kernel<<<NE / 4 / 256, 256>>>(ei, (const float4*)w, (const float4*)y);
    finalize_kernel<<<1, 1>>>((float*)d_out);
}

// round 2
// speedup vs baseline: 1.9256x; 1.9256x over previous
#include <cuda_runtime.h>
#include <cuda_fp16.h>
#include <math.h>

#define NN 100000
#define NE 3200000

// Scratch (device globals — no allocation allowed)
__device__ float  g_deg[NN];
__device__ double g_sum;
__device__ int    g_is64;
__device__ __align__(16) __half g_ynorm[NN * 16];   // y * rsqrt(degree), fp16, 32B/row

// ---------------------------------------------------------------------------
// Kernel 1: zero degree + sum, detect edge_index dtype (int64 => odd words 0)
// ---------------------------------------------------------------------------
__global__ void init_kernel(const unsigned int* __restrict__ ei_words) {
    int i = blockIdx.x * blockDim.x + threadIdx.x;
    if (i < NN) g_deg[i] = 0.0f;
    if (i == 0) {
        g_sum = 0.0;
        int is64 = 1;
        #pragma unroll
        for (int k = 1; k < 64; k += 2)
            if (ei_words[k] != 0u) is64 = 0;
        g_is64 = is64;
    }
}

// ---------------------------------------------------------------------------
// Kernel 2: degree = segment_sum(edge_weights, row)
// ---------------------------------------------------------------------------
__global__ void degree_kernel(const void* __restrict__ ei,
                              const float4* __restrict__ w4) {
    int t = blockIdx.x * blockDim.x + threadIdx.x;
    if (t >= NE / 4) return;
    float4 w = w4[t];
    int r0, r1, r2, r3;
    if (g_is64) {
        const longlong2* p = (const longlong2*)ei;
        longlong2 a = p[2 * t], b = p[2 * t + 1];
        r0 = (int)a.x; r1 = (int)a.y; r2 = (int)b.x; r3 = (int)b.y;
    } else {
        int4 a = ((const int4*)ei)[t];
        r0 = a.x; r1 = a.y; r2 = a.z; r3 = a.w;
    }
    atomicAdd(&g_deg[r0], w.x);
    atomicAdd(&g_deg[r1], w.y);
    atomicAdd(&g_deg[r2], w.z);
    atomicAdd(&g_deg[r3], w.w);
}

// ---------------------------------------------------------------------------
// Kernel 3: ynorm[n] = y[n] * rsqrt(degree[n]) in fp16 (32B per row)
// ---------------------------------------------------------------------------
__global__ void ynorm_kernel(const float4* __restrict__ y) {
    int i = blockIdx.x * blockDim.x + threadIdx.x;
    if (i >= NN) return;
    float dinv = rsqrtf(g_deg[i]);
    __half2* out = (__half2*)(g_ynorm + (size_t)i * 16);
    #pragma unroll
    for (int k = 0; k < 4; k++) {
        float4 v = y[i * 4 + k];
        out[2 * k]     = __floats2half2_rn(v.x * dinv, v.y * dinv);
        out[2 * k + 1] = __floats2half2_rn(v.z * dinv, v.w * dinv);
    }
}

// ---------------------------------------------------------------------------
// Kernel 4: per-edge weighted L2 norm of ynorm[r]-ynorm[c], reduced to scalar.
// 2 lanes per edge: each lane loads one uint4 (16B = 8 halves) of each row.
// 16 edges per warp per iteration -> coalesced 128B index loads.
// ---------------------------------------------------------------------------
#define EK_BLOCKS 3125
#define EK_ITER   8     // 3125 blocks * 8 warps * 16 edges * 8 iters = 3.2M

__global__ void __launch_bounds__(256)
edge_kernel(const void* __restrict__ ei, const float* __restrict__ w) {
    int tid    = blockIdx.x * blockDim.x + threadIdx.x;
    int warpId = tid >> 5;
    int lane   = threadIdx.x & 31;
    int gid    = lane >> 1;      // edge slot within the warp's 16
    int sub    = lane & 1;       // which 16B half of the 32B row
    int base   = warpId * (16 * EK_ITER);
    int is64   = g_is64;
    const uint4* yn = (const uint4*)g_ynorm;

    float acc = 0.0f;
    #pragma unroll 4
    for (int j = 0; j < EK_ITER; j++) {
        int e = base + j * 16 + gid;
        int r, c;
        if (is64) {
            const long long* p = (const long long*)ei;
            r = (int)p[e];
            c = (int)p[NE + e];
        } else {
            const int* p = (const int*)ei;
            r = p[e];
            c = p[NE + e];
        }
        float we = w[e];
        uint4 hr = yn[r * 2 + sub];
        uint4 hc = yn[c * 2 + sub];

        float s = 0.0f;
        {
            float2 a, b; float d;
            a = __half22float2(*(const __half2*)&hr.x);
            b = __half22float2(*(const __half2*)&hc.x);
            d = a.x - b.x; s += d * d; d = a.y - b.y; s += d * d;
            a = __half22float2(*(const __half2*)&hr.y);
            b = __half22float2(*(const __half2*)&hc.y);
            d = a.x - b.x; s += d * d; d = a.y - b.y; s += d * d;
            a = __half22float2(*(const __half2*)&hr.z);
            b = __half22float2(*(const __half2*)&hc.z);
            d = a.x - b.x; s += d * d; d = a.y - b.y; s += d * d;
            a = __half22float2(*(const __half2*)&hr.w);
            b = __half22float2(*(const __half2*)&hc.w);
            d = a.x - b.x; s += d * d; d = a.y - b.y; s += d * d;
        }
        s += __shfl_xor_sync(0xffffffffu, s, 1);
        if (sub == 0) acc += sqrtf(s) * we;
    }

    // block reduction
    #pragma unroll
    for (int off = 16; off; off >>= 1)
        acc += __shfl_down_sync(0xffffffffu, acc, off);
    __shared__ float warp_sums[8];
    int wid = threadIdx.x >> 5;
    if ((threadIdx.x & 31) == 0) warp_sums[wid] = acc;
    __syncthreads();
    if (wid == 0) {
        int l = threadIdx.x;
        float v = (l < 8) ? warp_sums[l] : 0.0f;
        #pragma unroll
        for (int off = 4; off; off >>= 1)
            v += __shfl_down_sync(0xffffffffu, v, off);
        if (l == 0) atomicAdd(&g_sum, (double)v);
    }
}

// ---------------------------------------------------------------------------
// Kernel 5: mean
// ---------------------------------------------------------------------------
__global__ void finalize_kernel(float* __restrict__ out) {
    out[0] = (float)(g_sum / (double)NE);
}

extern "C" void kernel_launch(void* const* d_in, const int* in_sizes, int n_in,
                              void* d_out, int out_size) {
    const void*  ei = d_in[0];                  // edge_index (2, NE)
    const float* w  = (const float*)d_in[1];    // edge_weights (NE,)
    const float* y  = (const float*)d_in[2];    // y (NN, 16)

    init_kernel<<<(NN + 255) / 256, 256>>>((const unsigned int*)ei);
    degree_kernel<<<NE / 4 / 256, 256>>>(ei, (const float4*)w);
    ynorm_kernel<<<(NN + 255) / 256, 256>>>((const float4*)y);
    edge_kernel<<<EK_BLOCKS, 256>>>(ei, w);
    finalize_kernel<<<1, 1>>>((float*)d_out);
}

// round 3
// speedup vs baseline: 1.9721x; 1.0241x over previous
#include <cuda_runtime.h>
#include <cuda_fp16.h>
#include <math.h>

#define NN 100000
#define NE 3200000

// Scratch (device globals; zero-initialized at load, and every kernel_launch
// invocation restores them to zero => deterministic under graph replay)
__device__ float  g_deg[NN];
__device__ double g_sum;
__device__ __align__(16) __half g_ynorm[NN * 16];   // y * rsqrt(degree), fp16, 32B/row

// Per-warp dtype detect: int64 little-endian values < 100000 => odd 32-bit
// words of the first 32 elements are all zero. 1 load + 1 ballot.
__device__ __forceinline__ int detect_is64(const void* ei) {
    int lane = threadIdx.x & 31;
    unsigned v = ((const unsigned*)ei)[2 * lane + 1];
    return __ballot_sync(0xffffffffu, v == 0u) == 0xffffffffu;
}

// ---------------------------------------------------------------------------
// Kernel 1: degree = segment_sum(edge_weights, row). g_deg arrives zeroed.
// ---------------------------------------------------------------------------
__global__ void degree_kernel(const void* __restrict__ ei,
                              const float4* __restrict__ w4) {
    int is64 = detect_is64(ei);
    int t = blockIdx.x * blockDim.x + threadIdx.x;   // grid sized exactly NE/4
    float4 w = w4[t];
    int r0, r1, r2, r3;
    if (is64) {
        const longlong2* p = (const longlong2*)ei;
        longlong2 a = p[2 * t], b = p[2 * t + 1];
        r0 = (int)a.x; r1 = (int)a.y; r2 = (int)b.x; r3 = (int)b.y;
    } else {
        int4 a = ((const int4*)ei)[t];
        r0 = a.x; r1 = a.y; r2 = a.z; r3 = a.w;
    }
    atomicAdd(&g_deg[r0], w.x);
    atomicAdd(&g_deg[r1], w.y);
    atomicAdd(&g_deg[r2], w.z);
    atomicAdd(&g_deg[r3], w.w);
}

// ---------------------------------------------------------------------------
// Kernel 2: ynorm[n] = y[n] * rsqrt(degree[n]) in fp16; re-zero g_deg.
// ---------------------------------------------------------------------------
__global__ void ynorm_kernel(const float4* __restrict__ y) {
    int i = blockIdx.x * blockDim.x + threadIdx.x;
    if (i >= NN) return;
    float dinv = rsqrtf(g_deg[i]);
    g_deg[i] = 0.0f;                                  // restore invariant
    __half2* out = (__half2*)(g_ynorm + (size_t)i * 16);
    #pragma unroll
    for (int k = 0; k < 4; k++) {
        float4 v = y[i * 4 + k];
        out[2 * k]     = __floats2half2_rn(v.x * dinv, v.y * dinv);
        out[2 * k + 1] = __floats2half2_rn(v.z * dinv, v.w * dinv);
    }
}

// ---------------------------------------------------------------------------
// Kernel 3: per-edge weighted L2 of ynorm[r]-ynorm[c], reduced to scalar.
// 2 lanes per edge (16B each of the 32B row). All indices+weights loaded
// first, then ALL 16 gathers issued back-to-back for maximum MLP.
// ---------------------------------------------------------------------------
#define EK_BLOCKS 3125
#define EK_ITER   8     // 3125 blocks * 8 warps * 16 edges * 8 iters = 3.2M

__global__ void __launch_bounds__(256)
edge_kernel(const void* __restrict__ ei, const float* __restrict__ w) {
    int is64   = detect_is64(ei);
    int tid    = blockIdx.x * blockDim.x + threadIdx.x;
    int warpId = tid >> 5;
    int lane   = threadIdx.x & 31;
    int gid    = lane >> 1;      // edge slot within the warp's 16
    int sub    = lane & 1;       // which 16B half of the 32B row
    int base   = warpId * (16 * EK_ITER);
    const uint4* yn = (const uint4*)g_ynorm;

    // Phase 1: all indices + weights (independent, coalesced)
    int r[EK_ITER], c[EK_ITER];
    float wv[EK_ITER];
    if (is64) {
        const long long* p = (const long long*)ei;
        #pragma unroll
        for (int j = 0; j < EK_ITER; j++) {
            int e = base + j * 16 + gid;
            r[j] = (int)p[e];
            c[j] = (int)p[NE + e];
        }
    } else {
        const int* p = (const int*)ei;
        #pragma unroll
        for (int j = 0; j < EK_ITER; j++) {
            int e = base + j * 16 + gid;
            r[j] = p[e];
            c[j] = p[NE + e];
        }
    }
    #pragma unroll
    for (int j = 0; j < EK_ITER; j++) wv[j] = w[base + j * 16 + gid];

    // Phase 2: all 16 gathers in flight
    uint4 hr[EK_ITER], hc[EK_ITER];
    #pragma unroll
    for (int j = 0; j < EK_ITER; j++) {
        hr[j] = yn[r[j] * 2 + sub];
        hc[j] = yn[c[j] * 2 + sub];
    }

    // Phase 3: compute
    float acc = 0.0f;
    #pragma unroll
    for (int j = 0; j < EK_ITER; j++) {
        float s = 0.0f;
        const __half2* a2 = (const __half2*)&hr[j];
        const __half2* b2 = (const __half2*)&hc[j];
        #pragma unroll
        for (int k = 0; k < 4; k++) {
            float2 a = __half22float2(a2[k]);
            float2 b = __half22float2(b2[k]);
            float d0 = a.x - b.x;
            float d1 = a.y - b.y;
            s += d0 * d0 + d1 * d1;
        }
        s += __shfl_xor_sync(0xffffffffu, s, 1);
        if (sub == 0) acc += sqrtf(s) * wv[j];
    }

    // Block reduction
    #pragma unroll
    for (int off = 16; off; off >>= 1)
        acc += __shfl_down_sync(0xffffffffu, acc, off);
    __shared__ float warp_sums[8];
    int wid = threadIdx.x >> 5;
    if (lane == 0) warp_sums[wid] = acc;
    __syncthreads();
    if (wid == 0) {
        float v = (lane < 8) ? warp_sums[lane] : 0.0f;
        #pragma unroll
        for (int off = 4; off; off >>= 1)
            v += __shfl_down_sync(0xffffffffu, v, off);
        if (lane == 0) atomicAdd(&g_sum, (double)v);
    }
}

// ---------------------------------------------------------------------------
// Kernel 4: mean; re-zero g_sum.
// ---------------------------------------------------------------------------
__global__ void finalize_kernel(float* __restrict__ out) {
    out[0] = (float)(g_sum / (double)NE);
    g_sum = 0.0;                                      // restore invariant
}

extern "C" void kernel_launch(void* const* d_in, const int* in_sizes, int n_in,
                              void* d_out, int out_size) {
    const void*  ei = d_in[0];                  // edge_index (2, NE)
    const float* w  = (const float*)d_in[1];    // edge_weights (NE,)
    const float* y  = (const float*)d_in[2];    // y (NN, 16)

    degree_kernel<<<NE / 4 / 256, 256>>>(ei, (const float4*)w);
    ynorm_kernel<<<(NN + 255) / 256, 256>>>((const float4*)y);
    edge_kernel<<<EK_BLOCKS, 256>>>(ei, w);
    finalize_kernel<<<1, 1>>>((float*)d_out);
}